// round 8
// baseline (speedup 1.0000x reference)
#include <cuda_runtime.h>
#include <cuda_bf16.h>
#include <stdint.h>

#define N_NODES  100000
#define N_EDGES  3200000
#define N_FEAT   128
#define HIDDEN   64
#define N_GRAPHS 256

// Padded CSC capacity: E + 3 per node + 8 slack for unroll-8 overread
#define CSC_CAP  (N_EDGES + 4 * N_NODES + 8)
#define NCHUNK   ((N_NODES + 255) / 256)     // 391 chunks of 256 nodes

// ---------------- device scratch ----------------
__device__ __align__(16) static __nv_bfloat162 g_P [N_NODES * 32];  // layer-1 messages
__device__ __align__(16) static __nv_bfloat162 g_P2[N_NODES * 32];  // layer-2 messages
__device__ __align__(16) static __nv_bfloat162 g_H1[N_NODES * 32];  // layer-1 out
__device__ __align__(16) static float g_pool[N_GRAPHS * 64];        // pooled sums
__device__ __align__(16) static int   g_csc[CSC_CAP];               // pad slots stay 0
__device__              static int   g_deg[N_NODES];
__device__              static int   g_rowptr[N_NODES];
__device__              static int   g_cursor[N_NODES];
__device__              static float g_dinv[N_NODES];
__device__              static int   g_csum[NCHUNK];

// ---------------- epoch grid barrier (all resident blocks of k_csc) --------------
__device__          static unsigned g_cnt;     // zero-init
__device__ volatile static unsigned g_epoch;   // zero-init

__device__ __forceinline__ void gbar() {
    __threadfence();
    __syncthreads();
    if (threadIdx.x == 0) {
        unsigned my = g_epoch;
        if (atomicAdd(&g_cnt, 1u) == gridDim.x - 1u) {
            g_cnt = 0;
            __threadfence();
            g_epoch = my + 1u;
        } else {
            while (g_epoch == my) __nanosleep(64);
        }
        __threadfence();
    }
    __syncthreads();
}

// ================= CSC build: one persistent kernel, 5 phases =================
__global__ void __launch_bounds__(256) k_csc(const int* __restrict__ eidx) {
    __shared__ int smi[16];
    int t = threadIdx.x;
    int gid = blockIdx.x * 256 + t;
    int gstride = gridDim.x * 256;
    const int4* src4 = (const int4*)eidx;
    const int4* dst4 = (const int4*)(eidx + N_EDGES);

    // P0: zero degree + pool accumulator
    for (int i = gid; i < N_NODES; i += gstride) g_deg[i] = 0;
    for (int i = gid; i < N_GRAPHS * 64; i += gstride) g_pool[i] = 0.f;
    gbar();

    // P1: degree histogram (4 edges/thread)
    for (int i = gid; i < N_EDGES / 4; i += gstride) {
        int4 d = dst4[i];
        atomicAdd(&g_deg[d.x], 1);
        atomicAdd(&g_deg[d.y], 1);
        atomicAdd(&g_deg[d.z], 1);
        atomicAdd(&g_deg[d.w], 1);
    }
    gbar();

    // P2: chunk-local scan of padded degrees (+ dinv)
    {
        int lane = t & 31, w = t >> 5;
        for (int c = blockIdx.x; c < NCHUNK; c += gridDim.x) {
            __syncthreads();
            int i = c * 256 + t;
            int v = 0;
            if (i < N_NODES) {
                int d = g_deg[i];
                g_dinv[i] = rsqrtf((float)(d + 1));
                v = (d + 3) & ~3;
            }
            int inc = v;
            #pragma unroll
            for (int o = 1; o < 32; o <<= 1) {
                int u = __shfl_up_sync(0xFFFFFFFFu, inc, o);
                if (lane >= o) inc += u;
            }
            if (lane == 31) smi[w] = inc;
            __syncthreads();
            if (t == 0) {
                int run = 0;
                #pragma unroll
                for (int j = 0; j < 8; j++) { int xx = smi[j]; smi[j] = run; run += xx; }
                g_csum[c] = run;
            }
            __syncthreads();
            if (i < N_NODES) g_rowptr[i] = inc + smi[w] - v;   // exclusive local
        }
    }
    gbar();

    // P3: chunk offsets + cursor init
    {
        int lane = t & 31, w = t >> 5;
        for (int c = blockIdx.x; c < NCHUNK; c += gridDim.x) {
            __syncthreads();
            int s = 0;
            for (int j = t; j < c; j += 256) s += g_csum[j];
            #pragma unroll
            for (int o = 16; o; o >>= 1) s += __shfl_down_sync(0xFFFFFFFFu, s, o);
            if (lane == 0) smi[w] = s;
            __syncthreads();
            if (t == 0) {
                int r = 0;
                #pragma unroll
                for (int j = 0; j < 8; j++) r += smi[j];
                smi[9] = r;
            }
            __syncthreads();
            int off = smi[9];
            int i = c * 256 + t;
            if (i < N_NODES) {
                int r = g_rowptr[i] + off;
                g_rowptr[i] = r;
                g_cursor[i] = r;
            }
        }
    }
    gbar();

    // P4: CSC bucket fill (4 edges/thread)
    for (int i = gid; i < N_EDGES / 4; i += gstride) {
        int4 s = src4[i];
        int4 d = dst4[i];
        g_csc[atomicAdd(&g_cursor[d.x], 1)] = s.x;
        g_csc[atomicAdd(&g_cursor[d.y], 1)] = s.y;
        g_csc[atomicAdd(&g_cursor[d.z], 1)] = s.z;
        g_csc[atomicAdd(&g_cursor[d.w], 1)] = s.w;
    }
}

// ---------------- f32x2 helpers ----------------
__device__ __forceinline__ unsigned long long dup_f32(float x) {
    unsigned long long r;
    unsigned xb = __float_as_uint(x);
    asm("mov.b64 %0, {%1, %1};" : "=l"(r) : "r"(xb));
    return r;
}
__device__ __forceinline__ void fma2(unsigned long long& acc, unsigned long long a,
                                     unsigned long long b) {
    asm("fma.rn.f32x2 %0, %1, %2, %0;" : "+l"(acc) : "l"(a), "l"(b));
}
__device__ __forceinline__ void unpack2(unsigned long long v, float& lo, float& hi) {
    asm("mov.b64 {%0, %1}, %2;" : "=f"(lo), "=f"(hi) : "l"(v));
}

__device__ __forceinline__ void emit_row(__nv_bfloat162* __restrict__ P,
                                         int row, int lane, float c0, float c1) {
    if (row < N_NODES) {
        float s = g_dinv[row];
        P[row * 32 + lane] = __floats2bfloat162_rn(c0 * s, c1 * s);
    }
}

// ---------------- GEMM1: P = (X[fp32,K=128] @ W1) * dinv, bf16 out ----------------
__global__ void k_gemm1(const float* __restrict__ X, const float* __restrict__ W) {
    extern __shared__ unsigned char dyn[];
    float2*     sW = (float2*)dyn;                 // 32KB
    ulonglong2* sx = (ulonglong2*)(dyn + 32768);   // 32KB
    const float2* W2 = (const float2*)W;
    for (int t = threadIdx.x; t < 128 * 32; t += 256) sW[t] = W2[t];
    __syncthreads();

    int warp = threadIdx.x >> 5, lane = threadIdx.x & 31;
    ulonglong2* sxA = sx + warp * 256;
    ulonglong2* sxB = sxA + 128;
    const int NG = (N_NODES + 63) >> 6;

    for (int g = blockIdx.x; g < NG; g += gridDim.x) {
        int row0 = g * 64 + warp * 8;
        #pragma unroll
        for (int j = 0; j < 4; j++) {
            int k = lane + 32 * j;
            float v[8];
            #pragma unroll
            for (int r = 0; r < 8; r++) {
                int rr = row0 + r; if (rr >= N_NODES) rr = N_NODES - 1;
                v[r] = X[(size_t)rr * 128 + k];
            }
            float4 fa = make_float4(v[0], v[1], v[2], v[3]);
            float4 fb = make_float4(v[4], v[5], v[6], v[7]);
            sxA[k] = *reinterpret_cast<ulonglong2*>(&fa);
            sxB[k] = *reinterpret_cast<ulonglong2*>(&fb);
        }
        __syncwarp();

        unsigned long long acc[8];
        #pragma unroll
        for (int i = 0; i < 8; i++) acc[i] = 0ull;

        #pragma unroll 4
        for (int k = 0; k < 128; k++) {
            float2 w = sW[k * 32 + lane];
            unsigned long long wxx = dup_f32(w.x);
            unsigned long long wyy = dup_f32(w.y);
            ulonglong2 a = sxA[k];
            ulonglong2 b = sxB[k];
            fma2(acc[0], a.x, wxx);
            fma2(acc[1], a.y, wxx);
            fma2(acc[2], a.x, wyy);
            fma2(acc[3], a.y, wyy);
            fma2(acc[4], b.x, wxx);
            fma2(acc[5], b.y, wxx);
            fma2(acc[6], b.x, wyy);
            fma2(acc[7], b.y, wyy);
        }

        #pragma unroll
        for (int h = 0; h < 4; h++) {
            int ia = (h < 2) ? h : h + 2;
            int ib = ia + 2;
            float l0, h0, l1, h1;
            unpack2(acc[ia], l0, h0);
            unpack2(acc[ib], l1, h1);
            emit_row(g_P, row0 + 2 * h,     lane, l0, l1);
            emit_row(g_P, row0 + 2 * h + 1, lane, h0, h1);
        }
        __syncwarp();
    }
}

// ---------------- GEMM2: P2 = (H1[bf16,K=64] @ W2) * dinv, bf16 out --------------
__global__ void k_gemm2(const float* __restrict__ W) {
    __shared__ float2     sW[64 * 32];      // 16KB
    __shared__ ulonglong2 sx[8 * 128];      // 16KB
    const float2* W2 = (const float2*)W;
    for (int t = threadIdx.x; t < 64 * 32; t += 256) sW[t] = W2[t];
    __syncthreads();

    int warp = threadIdx.x >> 5, lane = threadIdx.x & 31;
    ulonglong2* sxA = sx + warp * 128;
    ulonglong2* sxB = sxA + 64;
    const int NG = (N_NODES + 63) >> 6;

    for (int g = blockIdx.x; g < NG; g += gridDim.x) {
        int row0 = g * 64 + warp * 8;
        {
            float2 f[8];
            #pragma unroll
            for (int r = 0; r < 8; r++) {
                int rr = row0 + r; if (rr >= N_NODES) rr = N_NODES - 1;
                f[r] = __bfloat1622float2(g_H1[rr * 32 + lane]);
            }
            float4 a0 = make_float4(f[0].x, f[1].x, f[2].x, f[3].x);
            float4 a1 = make_float4(f[0].y, f[1].y, f[2].y, f[3].y);
            float4 b0 = make_float4(f[4].x, f[5].x, f[6].x, f[7].x);
            float4 b1 = make_float4(f[4].y, f[5].y, f[6].y, f[7].y);
            sxA[2 * lane]     = *reinterpret_cast<ulonglong2*>(&a0);
            sxA[2 * lane + 1] = *reinterpret_cast<ulonglong2*>(&a1);
            sxB[2 * lane]     = *reinterpret_cast<ulonglong2*>(&b0);
            sxB[2 * lane + 1] = *reinterpret_cast<ulonglong2*>(&b1);
        }
        __syncwarp();

        unsigned long long acc[8];
        #pragma unroll
        for (int i = 0; i < 8; i++) acc[i] = 0ull;

        #pragma unroll 4
        for (int k = 0; k < 64; k++) {
            float2 w = sW[k * 32 + lane];
            unsigned long long wxx = dup_f32(w.x);
            unsigned long long wyy = dup_f32(w.y);
            ulonglong2 a = sxA[k];
            ulonglong2 b = sxB[k];
            fma2(acc[0], a.x, wxx);
            fma2(acc[1], a.y, wxx);
            fma2(acc[2], a.x, wyy);
            fma2(acc[3], a.y, wyy);
            fma2(acc[4], b.x, wxx);
            fma2(acc[5], b.y, wxx);
            fma2(acc[6], b.x, wyy);
            fma2(acc[7], b.y, wyy);
        }

        #pragma unroll
        for (int h = 0; h < 4; h++) {
            int ia = (h < 2) ? h : h + 2;
            int ib = ia + 2;
            float l0, h0, l1, h1;
            unpack2(acc[ia], l0, h0);
            unpack2(acc[ib], l1, h1);
            emit_row(g_P2, row0 + 2 * h,     lane, l0, l1);
            emit_row(g_P2, row0 + 2 * h + 1, lane, h0, h1);
        }
        __syncwarp();
    }
}

// ---------------- gather macro body (bf16 messages, fp32 accumulate) --------------
__device__ __forceinline__ float2 gather_node(const __nv_bfloat162* __restrict__ P,
                                              int n, int lane) {
    int start = g_rowptr[n];
    int end = start + g_deg[n];
    float2 acc = __bfloat1622float2(P[n * 32 + lane]);   // self term
    for (int p = start; p < end; p += 8) {
        int4 sa = *reinterpret_cast<const int4*>(g_csc + p);
        int4 sb = *reinterpret_cast<const int4*>(g_csc + p + 4);
        float2 v0 = __bfloat1622float2(P[(size_t)sa.x * 32 + lane]);
        float2 v1 = __bfloat1622float2(P[(size_t)sa.y * 32 + lane]);
        float2 v2 = __bfloat1622float2(P[(size_t)sa.z * 32 + lane]);
        float2 v3 = __bfloat1622float2(P[(size_t)sa.w * 32 + lane]);
        float2 v4 = __bfloat1622float2(P[(size_t)sb.x * 32 + lane]);
        float2 v5 = __bfloat1622float2(P[(size_t)sb.y * 32 + lane]);
        float2 v6 = __bfloat1622float2(P[(size_t)sb.z * 32 + lane]);
        float2 v7 = __bfloat1622float2(P[(size_t)sb.w * 32 + lane]);
        int rem = end - p;
        acc.x += v0.x; acc.y += v0.y;
        if (rem > 1) { acc.x += v1.x; acc.y += v1.y; }
        if (rem > 2) { acc.x += v2.x; acc.y += v2.y; }
        if (rem > 3) { acc.x += v3.x; acc.y += v3.y; }
        if (rem > 4) { acc.x += v4.x; acc.y += v4.y; }
        if (rem > 5) { acc.x += v5.x; acc.y += v5.y; }
        if (rem > 6) { acc.x += v6.x; acc.y += v6.y; }
        if (rem > 7) { acc.x += v7.x; acc.y += v7.y; }
    }
    return acc;
}

// ---------------- gather layer 1 (relu, bf16 out) ----------------
__global__ void k_gather1(const float* __restrict__ bias) {
    int widx = (blockIdx.x * blockDim.x + threadIdx.x) >> 5;
    if (widx >= N_NODES) return;
    int lane = threadIdx.x & 31;
    float2 b = reinterpret_cast<const float2*>(bias)[lane];
    float dn = g_dinv[widx];
    float2 acc = gather_node(g_P, widx, lane);
    float ox = fmaxf(dn * acc.x + b.x, 0.f);
    float oy = fmaxf(dn * acc.y + b.y, 0.f);
    g_H1[widx * 32 + lane] = __floats2bfloat162_rn(ox, oy);
}

// ---------------- gather layer 2 fused with mean-pool accumulation ----------------
// Each warp walks 16 consecutive nodes (batch sorted => few graph transitions),
// accumulates the per-graph partial sum locally, flushes via 2 atomics/lane.
#define POOL_CHUNK 16
__global__ void k_gather2pool(const int* __restrict__ batch,
                              const float* __restrict__ bias) {
    int lane = threadIdx.x & 31;
    int warp = (blockIdx.x * blockDim.x + threadIdx.x) >> 5;
    int nwarps = (gridDim.x * blockDim.x) >> 5;
    float2 b = reinterpret_cast<const float2*>(bias)[lane];
    const int NC = (N_NODES + POOL_CHUNK - 1) / POOL_CHUNK;

    for (int c = warp; c < NC; c += nwarps) {
        int n0 = c * POOL_CHUNK;
        int n1 = n0 + POOL_CHUNK; if (n1 > N_NODES) n1 = N_NODES;
        int curg = batch[n0];
        float2 pacc = make_float2(0.f, 0.f);
        for (int n = n0; n < n1; n++) {
            float dn = g_dinv[n];
            float2 acc = gather_node(g_P2, n, lane);
            float ox = dn * acc.x + b.x;
            float oy = dn * acc.y + b.y;
            int gb = batch[n];
            if (gb != curg) {
                atomicAdd(&g_pool[curg * 64 + 2 * lane],     pacc.x);
                atomicAdd(&g_pool[curg * 64 + 2 * lane + 1], pacc.y);
                pacc = make_float2(0.f, 0.f);
                curg = gb;
            }
            pacc.x += ox; pacc.y += oy;
        }
        atomicAdd(&g_pool[curg * 64 + 2 * lane],     pacc.x);
        atomicAdd(&g_pool[curg * 64 + 2 * lane + 1], pacc.y);
    }
}

// ---------------- head: out[g] = dot(pool[g],Wl)/cnt[g] + bl ----------------
__device__ __forceinline__ int lbound(const int* __restrict__ a, int n, int key) {
    int lo = 0, hi = n;
    while (lo < hi) {
        int m = (lo + hi) >> 1;
        if (a[m] < key) lo = m + 1; else hi = m;
    }
    return lo;
}

__global__ void k_head(const int* __restrict__ batch, const float* __restrict__ Wl,
                       const float* __restrict__ bl, float* __restrict__ out) {
    __shared__ float sw[2];
    int g = blockIdx.x;       // 256 blocks
    int t = threadIdx.x;      // 64 threads
    int lane = t & 31;
    float v = g_pool[g * 64 + t] * Wl[t];
    #pragma unroll
    for (int o = 16; o; o >>= 1) v += __shfl_down_sync(0xFFFFFFFFu, v, o);
    if (lane == 0) sw[t >> 5] = v;
    __syncthreads();
    if (t == 0) {
        int lo = lbound(batch, N_NODES, g);
        int hi = lbound(batch, N_NODES, g + 1);
        int cnt = hi - lo; if (cnt < 1) cnt = 1;
        out[g] = (sw[0] + sw[1]) / (float)cnt + bl[0];
    }
}

// ---------------- launch: 6 kernels ----------------
extern "C" void kernel_launch(void* const* d_in, const int* in_sizes, int n_in,
                              void* d_out, int out_size) {
    const float* x     = (const float*)d_in[0];
    const int*   eidx  = (const int*)d_in[1];
    const int*   batch = (const int*)d_in[2];
    const float* W1    = (const float*)d_in[3];
    const float* b1    = (const float*)d_in[4];
    const float* W2    = (const float*)d_in[5];
    const float* b2    = (const float*)d_in[6];
    const float* Wl    = (const float*)d_in[7];
    const float* bl    = (const float*)d_in[8];
    float* out = (float*)d_out;

    cudaFuncSetAttribute(k_gemm1, cudaFuncAttributeMaxDynamicSharedMemorySize, 65536);

    int dev = 0, sms = 148;
    cudaGetDevice(&dev);
    cudaDeviceGetAttribute(&sms, cudaDevAttrMultiProcessorCount, dev);
    int bpm = 0;
    cudaOccupancyMaxActiveBlocksPerMultiprocessor(&bpm, k_csc, 256, 0);
    if (bpm < 1) bpm = 1; if (bpm > 8) bpm = 8;
    int cscGrid = sms * bpm;   // guaranteed co-resident for the grid barrier

    // 1) CSC build (persistent, 5 internal phases)
    k_csc<<<cscGrid, 256>>>(eidx);

    // 2) layer 1 GEMM + gather
    k_gemm1<<<444, 256, 65536>>>(x, W1);
    k_gather1<<<(N_NODES * 32 + 255) / 256, 256>>>(b1);

    // 3) layer 2 GEMM + gather fused with pool accumulation
    k_gemm2<<<592, 256>>>(W2);
    {
        int nwarpsNeeded = (N_NODES + POOL_CHUNK - 1) / POOL_CHUNK;   // 6250
        int blocks = (nwarpsNeeded * 32 + 255) / 256;                 // 782
        k_gather2pool<<<blocks, 256>>>(batch, b2);
    }

    // 4) head
    k_head<<<N_GRAPHS, 64>>>(batch, Wl, bl, out);
}

// round 10
// speedup vs baseline: 1.1023x; 1.1023x over previous
#include <cuda_runtime.h>
#include <cuda_bf16.h>
#include <stdint.h>

#define N_NODES  100000
#define N_EDGES  3200000
#define N_FEAT   128
#define HIDDEN   64
#define N_GRAPHS 256

// Padded CSC capacity: E + 3 per node + 8 slack for unroll-8 overread
#define CSC_CAP  (N_EDGES + 4 * N_NODES + 8)
#define NCHUNK1K ((N_NODES + 1023) / 1024)    // 98 chunks of 1024 nodes

// ---------------- device scratch ----------------
__device__ __align__(16) static __nv_bfloat162 g_P [N_NODES * 32];  // layer-1 messages
__device__ __align__(16) static __nv_bfloat162 g_P2[N_NODES * 32];  // layer-2 messages
__device__ __align__(16) static __nv_bfloat162 g_H1[N_NODES * 32];  // layer-1 out
__device__ __align__(16) static __nv_bfloat162 g_H2[N_NODES * 32];  // layer-2 out
__device__ __align__(16) static int   g_csc[CSC_CAP];               // pad slots stay 0
__device__              static int   g_deg[N_NODES];
__device__              static int   g_rowptr[N_NODES];
__device__              static int   g_cursor[N_NODES];
__device__              static float g_dinv[N_NODES];
__device__              static int   g_csum[NCHUNK1K];

// ---------------- epoch grid barrier (one block per SM => cheap) ----------------
__device__ static unsigned g_cnt;              // zero-init
__device__ static unsigned g_epoch;            // zero-init

__device__ __forceinline__ void gbar() {
    __threadfence();
    __syncthreads();
    if (threadIdx.x == 0) {
        unsigned my = atomicAdd(&g_epoch, 0u);              // acquire-ish read
        if (atomicAdd(&g_cnt, 1u) == gridDim.x - 1u) {
            atomicExch(&g_cnt, 0u);
            atomicExch(&g_epoch, my + 1u);                  // release
        } else {
            while (atomicAdd(&g_epoch, 0u) == my) __nanosleep(64);
        }
        __threadfence();
    }
    __syncthreads();
}

// ================= CSC build: one persistent kernel (grid = #SMs) =================
__global__ void __launch_bounds__(1024, 1) k_build(const int* __restrict__ eidx) {
    __shared__ int smi[34];
    int t = threadIdx.x;
    int lane = t & 31, w = t >> 5;
    int gid = blockIdx.x * 1024 + t;
    int gstride = gridDim.x * 1024;
    const int4* src4 = (const int4*)eidx;
    const int4* dst4 = (const int4*)(eidx + N_EDGES);

    // ---- P0: zero degree ----
    for (int i = gid; i < N_NODES; i += gstride) g_deg[i] = 0;
    gbar();

    // ---- P1: degree histogram (4 edges/thread) ----
    for (int i = gid; i < N_EDGES / 4; i += gstride) {
        int4 d = dst4[i];
        atomicAdd(&g_deg[d.x], 1);
        atomicAdd(&g_deg[d.y], 1);
        atomicAdd(&g_deg[d.z], 1);
        atomicAdd(&g_deg[d.w], 1);
    }
    gbar();

    // ---- P2: per-chunk (1024-wide) local scan of padded degrees + dinv ----
    for (int c = blockIdx.x; c < NCHUNK1K; c += gridDim.x) {
        int i = c * 1024 + t;
        int v = 0;
        if (i < N_NODES) {
            int d = g_deg[i];
            g_dinv[i] = rsqrtf((float)(d + 1));      // self-loop +1
            v = (d + 3) & ~3;                        // pad segment to multiple of 4
        }
        int inc = v;
        #pragma unroll
        for (int o = 1; o < 32; o <<= 1) {
            int u = __shfl_up_sync(0xFFFFFFFFu, inc, o);
            if (lane >= o) inc += u;
        }
        if (lane == 31) smi[w] = inc;                // 32 warp sums
        __syncthreads();
        if (t < 32) {
            int s = smi[t];
            int inc2 = s;
            #pragma unroll
            for (int o = 1; o < 32; o <<= 1) {
                int u = __shfl_up_sync(0xFFFFFFFFu, inc2, o);
                if (t >= o) inc2 += u;
            }
            smi[t] = inc2 - s;                       // exclusive warp offsets
        }
        __syncthreads();
        int excl = (inc - v) + smi[w];               // block-local exclusive
        if (i < N_NODES) g_rowptr[i] = excl;
        if (t == 1023) g_csum[c] = excl + v;         // chunk total
        __syncthreads();
    }
    gbar();

    // ---- P3: chunk offsets (direct summation) + cursor init ----
    for (int c = blockIdx.x; c < NCHUNK1K; c += gridDim.x) {
        if (t < 32) {
            int s = 0;
            for (int j = t; j < c; j += 32) s += g_csum[j];
            #pragma unroll
            for (int o = 16; o; o >>= 1) s += __shfl_down_sync(0xFFFFFFFFu, s, o);
            if (t == 0) smi[33] = s;
        }
        __syncthreads();
        int off = smi[33];
        int i = c * 1024 + t;
        if (i < N_NODES) {
            int r = g_rowptr[i] + off;
            g_rowptr[i] = r;
            g_cursor[i] = r;
        }
        __syncthreads();
    }
    gbar();

    // ---- P4: CSC bucket fill (4 edges/thread) ----
    for (int i = gid; i < N_EDGES / 4; i += gstride) {
        int4 s = src4[i];
        int4 d = dst4[i];
        g_csc[atomicAdd(&g_cursor[d.x], 1)] = s.x;
        g_csc[atomicAdd(&g_cursor[d.y], 1)] = s.y;
        g_csc[atomicAdd(&g_cursor[d.z], 1)] = s.z;
        g_csc[atomicAdd(&g_cursor[d.w], 1)] = s.w;
    }
}

// ---------------- f32x2 helpers ----------------
__device__ __forceinline__ unsigned long long dup_f32(float x) {
    unsigned long long r;
    unsigned xb = __float_as_uint(x);
    asm("mov.b64 %0, {%1, %1};" : "=l"(r) : "r"(xb));
    return r;
}
__device__ __forceinline__ void fma2(unsigned long long& acc, unsigned long long a,
                                     unsigned long long b) {
    asm("fma.rn.f32x2 %0, %1, %2, %0;" : "+l"(acc) : "l"(a), "l"(b));
}
__device__ __forceinline__ void unpack2(unsigned long long v, float& lo, float& hi) {
    asm("mov.b64 {%0, %1}, %2;" : "=f"(lo), "=f"(hi) : "l"(v));
}

__device__ __forceinline__ void emit_row(__nv_bfloat162* __restrict__ P,
                                         int row, int lane, float c0, float c1) {
    if (row < N_NODES) {
        float s = g_dinv[row];
        P[row * 32 + lane] = __floats2bfloat162_rn(c0 * s, c1 * s);
    }
}

// ---------------- GEMM1: P = (X[fp32,K=128] @ W1) * dinv, bf16 out ----------------
__global__ void k_gemm1(const float* __restrict__ X, const float* __restrict__ W) {
    extern __shared__ unsigned char dyn[];
    float2*     sW = (float2*)dyn;                 // 32KB
    ulonglong2* sx = (ulonglong2*)(dyn + 32768);   // 32KB
    const float2* W2 = (const float2*)W;
    for (int t = threadIdx.x; t < 128 * 32; t += 256) sW[t] = W2[t];
    __syncthreads();

    int warp = threadIdx.x >> 5, lane = threadIdx.x & 31;
    ulonglong2* sxA = sx + warp * 256;
    ulonglong2* sxB = sxA + 128;
    const int NG = (N_NODES + 63) >> 6;

    for (int g = blockIdx.x; g < NG; g += gridDim.x) {
        int row0 = g * 64 + warp * 8;
        #pragma unroll
        for (int j = 0; j < 4; j++) {
            int k = lane + 32 * j;
            float v[8];
            #pragma unroll
            for (int r = 0; r < 8; r++) {
                int rr = row0 + r; if (rr >= N_NODES) rr = N_NODES - 1;
                v[r] = X[(size_t)rr * 128 + k];
            }
            float4 fa = make_float4(v[0], v[1], v[2], v[3]);
            float4 fb = make_float4(v[4], v[5], v[6], v[7]);
            sxA[k] = *reinterpret_cast<ulonglong2*>(&fa);
            sxB[k] = *reinterpret_cast<ulonglong2*>(&fb);
        }
        __syncwarp();

        unsigned long long acc[8];
        #pragma unroll
        for (int i = 0; i < 8; i++) acc[i] = 0ull;

        #pragma unroll 4
        for (int k = 0; k < 128; k++) {
            float2 w = sW[k * 32 + lane];
            unsigned long long wxx = dup_f32(w.x);
            unsigned long long wyy = dup_f32(w.y);
            ulonglong2 a = sxA[k];
            ulonglong2 b = sxB[k];
            fma2(acc[0], a.x, wxx);
            fma2(acc[1], a.y, wxx);
            fma2(acc[2], a.x, wyy);
            fma2(acc[3], a.y, wyy);
            fma2(acc[4], b.x, wxx);
            fma2(acc[5], b.y, wxx);
            fma2(acc[6], b.x, wyy);
            fma2(acc[7], b.y, wyy);
        }

        #pragma unroll
        for (int h = 0; h < 4; h++) {
            int ia = (h < 2) ? h : h + 2;
            int ib = ia + 2;
            float l0, h0, l1, h1;
            unpack2(acc[ia], l0, h0);
            unpack2(acc[ib], l1, h1);
            emit_row(g_P, row0 + 2 * h,     lane, l0, l1);
            emit_row(g_P, row0 + 2 * h + 1, lane, h0, h1);
        }
        __syncwarp();
    }
}

// ---------------- GEMM2: P2 = (H1[bf16,K=64] @ W2) * dinv, bf16 out --------------
__global__ void k_gemm2(const float* __restrict__ W) {
    __shared__ float2     sW[64 * 32];      // 16KB
    __shared__ ulonglong2 sx[8 * 128];      // 16KB
    const float2* W2 = (const float2*)W;
    for (int t = threadIdx.x; t < 64 * 32; t += 256) sW[t] = W2[t];
    __syncthreads();

    int warp = threadIdx.x >> 5, lane = threadIdx.x & 31;
    ulonglong2* sxA = sx + warp * 128;
    ulonglong2* sxB = sxA + 64;
    const int NG = (N_NODES + 63) >> 6;

    for (int g = blockIdx.x; g < NG; g += gridDim.x) {
        int row0 = g * 64 + warp * 8;
        {
            float2 f[8];
            #pragma unroll
            for (int r = 0; r < 8; r++) {
                int rr = row0 + r; if (rr >= N_NODES) rr = N_NODES - 1;
                f[r] = __bfloat1622float2(g_H1[rr * 32 + lane]);
            }
            float4 a0 = make_float4(f[0].x, f[1].x, f[2].x, f[3].x);
            float4 a1 = make_float4(f[0].y, f[1].y, f[2].y, f[3].y);
            float4 b0 = make_float4(f[4].x, f[5].x, f[6].x, f[7].x);
            float4 b1 = make_float4(f[4].y, f[5].y, f[6].y, f[7].y);
            sxA[2 * lane]     = *reinterpret_cast<ulonglong2*>(&a0);
            sxA[2 * lane + 1] = *reinterpret_cast<ulonglong2*>(&a1);
            sxB[2 * lane]     = *reinterpret_cast<ulonglong2*>(&b0);
            sxB[2 * lane + 1] = *reinterpret_cast<ulonglong2*>(&b1);
        }
        __syncwarp();

        unsigned long long acc[8];
        #pragma unroll
        for (int i = 0; i < 8; i++) acc[i] = 0ull;

        #pragma unroll 4
        for (int k = 0; k < 64; k++) {
            float2 w = sW[k * 32 + lane];
            unsigned long long wxx = dup_f32(w.x);
            unsigned long long wyy = dup_f32(w.y);
            ulonglong2 a = sxA[k];
            ulonglong2 b = sxB[k];
            fma2(acc[0], a.x, wxx);
            fma2(acc[1], a.y, wxx);
            fma2(acc[2], a.x, wyy);
            fma2(acc[3], a.y, wyy);
            fma2(acc[4], b.x, wxx);
            fma2(acc[5], b.y, wxx);
            fma2(acc[6], b.x, wyy);
            fma2(acc[7], b.y, wyy);
        }

        #pragma unroll
        for (int h = 0; h < 4; h++) {
            int ia = (h < 2) ? h : h + 2;
            int ib = ia + 2;
            float l0, h0, l1, h1;
            unpack2(acc[ia], l0, h0);
            unpack2(acc[ib], l1, h1);
            emit_row(g_P2, row0 + 2 * h,     lane, l0, l1);
            emit_row(g_P2, row0 + 2 * h + 1, lane, h0, h1);
        }
        __syncwarp();
    }
}

// ---------------- gather-sum aggregation (bf16 messages, fp32 accumulate) ---------
template <int RELU>
__global__ void k_gather(const __nv_bfloat162* __restrict__ P,
                         __nv_bfloat162* __restrict__ Hout,
                         const float* __restrict__ bias) {
    int widx = (blockIdx.x * blockDim.x + threadIdx.x) >> 5;
    if (widx >= N_NODES) return;
    int lane = threadIdx.x & 31;

    float dn = g_dinv[widx];
    int start = g_rowptr[widx];
    int end = start + g_deg[widx];

    float2 acc = __bfloat1622float2(P[widx * 32 + lane]);   // self term

    for (int p = start; p < end; p += 8) {
        int4 sa = *reinterpret_cast<const int4*>(g_csc + p);
        int4 sb = *reinterpret_cast<const int4*>(g_csc + p + 4);
        float2 v0 = __bfloat1622float2(P[(size_t)sa.x * 32 + lane]);
        float2 v1 = __bfloat1622float2(P[(size_t)sa.y * 32 + lane]);
        float2 v2 = __bfloat1622float2(P[(size_t)sa.z * 32 + lane]);
        float2 v3 = __bfloat1622float2(P[(size_t)sa.w * 32 + lane]);
        float2 v4 = __bfloat1622float2(P[(size_t)sb.x * 32 + lane]);
        float2 v5 = __bfloat1622float2(P[(size_t)sb.y * 32 + lane]);
        float2 v6 = __bfloat1622float2(P[(size_t)sb.z * 32 + lane]);
        float2 v7 = __bfloat1622float2(P[(size_t)sb.w * 32 + lane]);
        int rem = end - p;
        acc.x += v0.x; acc.y += v0.y;
        if (rem > 1) { acc.x += v1.x; acc.y += v1.y; }
        if (rem > 2) { acc.x += v2.x; acc.y += v2.y; }
        if (rem > 3) { acc.x += v3.x; acc.y += v3.y; }
        if (rem > 4) { acc.x += v4.x; acc.y += v4.y; }
        if (rem > 5) { acc.x += v5.x; acc.y += v5.y; }
        if (rem > 6) { acc.x += v6.x; acc.y += v6.y; }
        if (rem > 7) { acc.x += v7.x; acc.y += v7.y; }
    }

    float2 b = reinterpret_cast<const float2*>(bias)[lane];
    float ox = dn * acc.x + b.x;
    float oy = dn * acc.y + b.y;
    if (RELU) { ox = fmaxf(ox, 0.f); oy = fmaxf(oy, 0.f); }
    Hout[widx * 32 + lane] = __floats2bfloat162_rn(ox, oy);
}

// ---------------- pool (mean per graph, bf16 in) + final linear ----------------
__device__ __forceinline__ int lbound(const int* __restrict__ a, int n, int key) {
    int lo = 0, hi = n;
    while (lo < hi) {
        int m = (lo + hi) >> 1;
        if (a[m] < key) lo = m + 1; else hi = m;
    }
    return lo;
}

__global__ void k_pool(const int* __restrict__ batch,
                       const float* __restrict__ Wl, const float* __restrict__ bl,
                       float* __restrict__ out) {
    __shared__ float2 sm[256];               // 8 partitions x 32 col-pairs
    int g = blockIdx.x;
    int t = threadIdx.x;                     // 256 threads
    int lo = lbound(batch, N_NODES, g);
    int hi = lbound(batch, N_NODES, g + 1);

    int cp   = t & 31;
    int part = t >> 5;
    float2 s = make_float2(0.f, 0.f);
    for (int n = lo + part; n < hi; n += 8) {
        float2 v = __bfloat1622float2(g_H2[(size_t)n * 32 + cp]);
        s.x += v.x; s.y += v.y;
    }
    sm[t] = s;
    __syncthreads();
    if (t < 32) {
        float2 v = sm[t];
        #pragma unroll
        for (int p = 1; p < 8; p++) {
            float2 u = sm[t + 32 * p];
            v.x += u.x; v.y += u.y;
        }
        int cnt = hi - lo;
        float inv = 1.f / (float)(cnt > 0 ? cnt : 1);
        float2 w = reinterpret_cast<const float2*>(Wl)[t];
        sm[t] = make_float2(v.x * inv * w.x + v.y * inv * w.y, 0.f);
    }
    __syncthreads();
    if (t == 0) {
        float r = 0.f;
        #pragma unroll
        for (int c = 0; c < 32; c++) r += sm[c].x;
        out[g] = r + bl[0];
    }
}

// ---------------- launch: 6 kernels ----------------
extern "C" void kernel_launch(void* const* d_in, const int* in_sizes, int n_in,
                              void* d_out, int out_size) {
    const float* x     = (const float*)d_in[0];
    const int*   eidx  = (const int*)d_in[1];
    const int*   batch = (const int*)d_in[2];
    const float* W1    = (const float*)d_in[3];
    const float* b1    = (const float*)d_in[4];
    const float* W2    = (const float*)d_in[5];
    const float* b2    = (const float*)d_in[6];
    const float* Wl    = (const float*)d_in[7];
    const float* bl    = (const float*)d_in[8];
    float* out = (float*)d_out;

    cudaFuncSetAttribute(k_gemm1, cudaFuncAttributeMaxDynamicSharedMemorySize, 65536);

    __nv_bfloat162* H1v; cudaGetSymbolAddress((void**)&H1v, g_H1);
    __nv_bfloat162* H2v; cudaGetSymbolAddress((void**)&H2v, g_H2);
    __nv_bfloat162* Pv;  cudaGetSymbolAddress((void**)&Pv,  g_P);
    __nv_bfloat162* P2v; cudaGetSymbolAddress((void**)&P2v, g_P2);

    int dev = 0, sms = 148;
    cudaGetDevice(&dev);
    cudaDeviceGetAttribute(&sms, cudaDevAttrMultiProcessorCount, dev);

    // 1) CSC build: persistent, one block per SM (co-residency guaranteed)
    k_build<<<sms, 1024>>>(eidx);

    // 2) layer 1
    k_gemm1<<<444, 256, 65536>>>(x, W1);
    k_gather<1><<<(N_NODES * 32 + 255) / 256, 256>>>(Pv, H1v, b1);

    // 3) layer 2
    k_gemm2<<<592, 256>>>(W2);
    k_gather<0><<<(N_NODES * 32 + 255) / 256, 256>>>(P2v, H2v, b2);

    // 4) pool + head
    k_pool<<<N_GRAPHS, 256>>>(batch, Wl, bl, out);
}

// round 12
// speedup vs baseline: 1.2773x; 1.1588x over previous
#include <cuda_runtime.h>
#include <cuda_bf16.h>
#include <stdint.h>

#define N_NODES  100000
#define N_EDGES  3200000
#define N_FEAT   128
#define HIDDEN   64
#define N_GRAPHS 256

// Padded CSC capacity: E + 3 per node + 8 slack for unroll-8 overread
#define CSC_CAP  (N_EDGES + 4 * N_NODES + 8)

// ---------------- device scratch ----------------
__device__ __align__(16) static __nv_bfloat162 g_P [N_NODES * 32];  // layer-1 messages
__device__ __align__(16) static __nv_bfloat162 g_P2[N_NODES * 32];  // layer-2 messages
__device__ __align__(16) static __nv_bfloat162 g_H1[N_NODES * 32];  // layer-1 out
__device__ __align__(16) static __nv_bfloat162 g_H2[N_NODES * 32];  // layer-2 out
__device__ __align__(16) static int   g_csc[CSC_CAP];               // pad slots stay 0
__device__              static int   g_deg[N_NODES];
__device__              static int   g_rowptr[N_NODES];
__device__              static int   g_cursor[N_NODES];
__device__              static float g_dinv[N_NODES];
__device__              static int   g_bsum[128];

// ---------------- init ----------------
__global__ void k_zero_deg() {
    int i = blockIdx.x * blockDim.x + threadIdx.x;
    if (i < N_NODES) g_deg[i] = 0;
}

// ---------------- degree histogram, 4 edges/thread ----------------
__global__ void k_count(const int4* __restrict__ dst4) {
    int i = blockIdx.x * blockDim.x + threadIdx.x;
    if (i < N_EDGES / 4) {
        int4 d = dst4[i];
        atomicAdd(&g_deg[d.x], 1);
        atomicAdd(&g_deg[d.y], 1);
        atomicAdd(&g_deg[d.z], 1);
        atomicAdd(&g_deg[d.w], 1);
    }
}

// ---------------- exclusive scan of padded degrees (+ dinv fused) ----------------
#define SCAN_B 1024
#define SCAN_NB ((N_NODES + SCAN_B - 1) / SCAN_B)   // 98

__global__ void k_scanA() {
    __shared__ int sm[SCAN_B];
    int i = blockIdx.x * SCAN_B + threadIdx.x;
    int v = 0;
    if (i < N_NODES) {
        int d = g_deg[i];
        g_dinv[i] = rsqrtf((float)(d + 1));          // fused dinv (self-loop +1)
        v = (d + 3) & ~3;                            // pad segment to multiple of 4
    }
    sm[threadIdx.x] = v;
    __syncthreads();
    #pragma unroll
    for (int off = 1; off < SCAN_B; off <<= 1) {
        int t = (threadIdx.x >= off) ? sm[threadIdx.x - off] : 0;
        __syncthreads();
        sm[threadIdx.x] += t;
        __syncthreads();
    }
    int inc = sm[threadIdx.x];
    if (i < N_NODES) g_rowptr[i] = inc - v;
    if (threadIdx.x == SCAN_B - 1) g_bsum[blockIdx.x] = inc;
}

// scanC with scanB merged: each block computes its own bsum-prefix directly.
__global__ void k_scanC() {
    __shared__ int soff;
    int c = blockIdx.x;
    if (threadIdx.x < 32) {
        int s = 0;
        for (int j = threadIdx.x; j < c; j += 32) s += g_bsum[j];
        #pragma unroll
        for (int o = 16; o; o >>= 1) s += __shfl_down_sync(0xFFFFFFFFu, s, o);
        if (threadIdx.x == 0) soff = s;
    }
    __syncthreads();
    int i = c * SCAN_B + threadIdx.x;
    if (i < N_NODES) {
        int r = g_rowptr[i] + soff;
        g_rowptr[i] = r;
        g_cursor[i] = r;
    }
}

// ---------------- CSC bucket fill, 4 edges/thread ----------------
__global__ void k_fill(const int4* __restrict__ src4, const int4* __restrict__ dst4) {
    int i = blockIdx.x * blockDim.x + threadIdx.x;
    if (i < N_EDGES / 4) {
        int4 s = src4[i];
        int4 d = dst4[i];
        g_csc[atomicAdd(&g_cursor[d.x], 1)] = s.x;
        g_csc[atomicAdd(&g_cursor[d.y], 1)] = s.y;
        g_csc[atomicAdd(&g_cursor[d.z], 1)] = s.z;
        g_csc[atomicAdd(&g_cursor[d.w], 1)] = s.w;
    }
}

// ---------------- tensor-core GEMM: P = (A @ W) * dinv, bf16 out ----------------
// mma.sync.aligned.m16n8k16.row.col.f32.bf16.bf16.f32
// Warp tile: 16 rows x 64 cols. A fragments straight from global
// (fp32->bf16 cvt inline for layer 1; H1 already bf16 for layer 2).
// B staged in smem transposed [n][k], stride K+8 elems => conflict-free.

__device__ __forceinline__ unsigned cvt_pack_bf2(float hi, float lo) {
    unsigned r;
    asm("cvt.rn.bf16x2.f32 %0, %1, %2;" : "=r"(r) : "f"(hi), "f"(lo));
    return r;
}

__device__ __forceinline__ void mma16816(float* d, unsigned a0, unsigned a1,
                                         unsigned a2, unsigned a3,
                                         unsigned b0, unsigned b1) {
    asm("mma.sync.aligned.m16n8k16.row.col.f32.bf16.bf16.f32 "
        "{%0,%1,%2,%3}, {%4,%5,%6,%7}, {%8,%9}, {%0,%1,%2,%3};"
        : "+f"(d[0]), "+f"(d[1]), "+f"(d[2]), "+f"(d[3])
        : "r"(a0), "r"(a1), "r"(a2), "r"(a3), "r"(b0), "r"(b1));
}

template <int K, bool A_FP32>
__global__ void k_mma(const void* __restrict__ Asrc, const float* __restrict__ W,
                      __nv_bfloat162* __restrict__ Pout) {
    constexpr int BSTRIDE = K + 8;                      // conflict-free LDS pattern
    __shared__ __nv_bfloat16 sB[64 * BSTRIDE];          // K=128: 17.4KB, K=64: 9.2KB

    for (int idx = threadIdx.x; idx < K * 64; idx += blockDim.x) {
        int k = idx >> 6, n = idx & 63;                 // W row-major [K][64]
        sB[n * BSTRIDE + k] = __float2bfloat16(W[idx]);
    }
    __syncthreads();

    int warp = threadIdx.x >> 5, lane = threadIdx.x & 31;
    int l4 = lane >> 2, lm = lane & 3;
    const int NTB = (N_NODES + 127) / 128;              // 782 blocks of 128 rows

    for (int tb = blockIdx.x; tb < NTB; tb += gridDim.x) {
        int row0 = tb * 128 + warp * 16;
        int ra = row0 + l4;                             // rows for d0/d1
        int rb = ra + 8;                                // rows for d2/d3
        int ca = ra < N_NODES ? ra : N_NODES - 1;       // clamped load rows
        int cb = rb < N_NODES ? rb : N_NODES - 1;

        float acc[32];
        #pragma unroll
        for (int i = 0; i < 32; i++) acc[i] = 0.f;

        #pragma unroll
        for (int ks = 0; ks < K / 16; ks++) {
            int k0 = ks * 16 + lm * 2;
            unsigned a0, a1, a2, a3;
            if (A_FP32) {
                const float* X = (const float*)Asrc;
                float2 fa = *(const float2*)(X + (size_t)ca * K + k0);
                float2 fb = *(const float2*)(X + (size_t)cb * K + k0);
                float2 fc = *(const float2*)(X + (size_t)ca * K + k0 + 8);
                float2 fd = *(const float2*)(X + (size_t)cb * K + k0 + 8);
                a0 = cvt_pack_bf2(fa.y, fa.x);          // hi = k0+1, lo = k0
                a1 = cvt_pack_bf2(fb.y, fb.x);
                a2 = cvt_pack_bf2(fc.y, fc.x);
                a3 = cvt_pack_bf2(fd.y, fd.x);
            } else {
                const __nv_bfloat16* H = (const __nv_bfloat16*)Asrc;
                a0 = *(const unsigned*)(H + (size_t)ca * K + k0);
                a1 = *(const unsigned*)(H + (size_t)cb * K + k0);
                a2 = *(const unsigned*)(H + (size_t)ca * K + k0 + 8);
                a3 = *(const unsigned*)(H + (size_t)cb * K + k0 + 8);
            }
            #pragma unroll
            for (int nt = 0; nt < 8; nt++) {
                const __nv_bfloat16* bp = sB + (nt * 8 + l4) * BSTRIDE + k0;
                unsigned b0 = *(const unsigned*)bp;       // (k0,n),(k0+1,n)
                unsigned b1 = *(const unsigned*)(bp + 8); // (k0+8,n),(k0+9,n)
                mma16816(&acc[nt * 4], a0, a1, a2, a3, b0, b1);
            }
        }

        float da = g_dinv[ca], db = g_dinv[cb];
        #pragma unroll
        for (int nt = 0; nt < 8; nt++) {
            int cp = nt * 4 + lm;                       // col-pair index (c0/2)
            if (ra < N_NODES)
                Pout[ra * 32 + cp] = __floats2bfloat162_rn(acc[nt*4+0]*da, acc[nt*4+1]*da);
            if (rb < N_NODES)
                Pout[rb * 32 + cp] = __floats2bfloat162_rn(acc[nt*4+2]*db, acc[nt*4+3]*db);
        }
    }
}

// ---------------- gather-sum aggregation (bf16 messages, fp32 accumulate) ---------
template <int RELU>
__global__ void k_gather(const __nv_bfloat162* __restrict__ P,
                         __nv_bfloat162* __restrict__ Hout,
                         const float* __restrict__ bias) {
    int widx = (blockIdx.x * blockDim.x + threadIdx.x) >> 5;
    if (widx >= N_NODES) return;
    int lane = threadIdx.x & 31;

    float dn = g_dinv[widx];
    int start = g_rowptr[widx];
    int end = start + g_deg[widx];

    float2 acc = __bfloat1622float2(P[widx * 32 + lane]);   // self term

    for (int p = start; p < end; p += 8) {
        int4 sa = *reinterpret_cast<const int4*>(g_csc + p);
        int4 sb = *reinterpret_cast<const int4*>(g_csc + p + 4);
        float2 v0 = __bfloat1622float2(P[(size_t)sa.x * 32 + lane]);
        float2 v1 = __bfloat1622float2(P[(size_t)sa.y * 32 + lane]);
        float2 v2 = __bfloat1622float2(P[(size_t)sa.z * 32 + lane]);
        float2 v3 = __bfloat1622float2(P[(size_t)sa.w * 32 + lane]);
        float2 v4 = __bfloat1622float2(P[(size_t)sb.x * 32 + lane]);
        float2 v5 = __bfloat1622float2(P[(size_t)sb.y * 32 + lane]);
        float2 v6 = __bfloat1622float2(P[(size_t)sb.z * 32 + lane]);
        float2 v7 = __bfloat1622float2(P[(size_t)sb.w * 32 + lane]);
        int rem = end - p;
        acc.x += v0.x; acc.y += v0.y;
        if (rem > 1) { acc.x += v1.x; acc.y += v1.y; }
        if (rem > 2) { acc.x += v2.x; acc.y += v2.y; }
        if (rem > 3) { acc.x += v3.x; acc.y += v3.y; }
        if (rem > 4) { acc.x += v4.x; acc.y += v4.y; }
        if (rem > 5) { acc.x += v5.x; acc.y += v5.y; }
        if (rem > 6) { acc.x += v6.x; acc.y += v6.y; }
        if (rem > 7) { acc.x += v7.x; acc.y += v7.y; }
    }

    float2 b = reinterpret_cast<const float2*>(bias)[lane];
    float ox = dn * acc.x + b.x;
    float oy = dn * acc.y + b.y;
    if (RELU) { ox = fmaxf(ox, 0.f); oy = fmaxf(oy, 0.f); }
    Hout[widx * 32 + lane] = __floats2bfloat162_rn(ox, oy);
}

// ---------------- pool (mean per graph, bf16 in) + final linear ----------------
__device__ __forceinline__ int lbound(const int* __restrict__ a, int n, int key) {
    int lo = 0, hi = n;
    while (lo < hi) {
        int m = (lo + hi) >> 1;
        if (a[m] < key) lo = m + 1; else hi = m;
    }
    return lo;
}

__global__ void k_pool(const int* __restrict__ batch,
                       const float* __restrict__ Wl, const float* __restrict__ bl,
                       float* __restrict__ out) {
    __shared__ float2 sm[256];               // 8 partitions x 32 col-pairs
    int g = blockIdx.x;
    int t = threadIdx.x;                     // 256 threads
    int lo = lbound(batch, N_NODES, g);
    int hi = lbound(batch, N_NODES, g + 1);

    int cp   = t & 31;
    int part = t >> 5;
    float2 s = make_float2(0.f, 0.f);
    for (int n = lo + part; n < hi; n += 8) {
        float2 v = __bfloat1622float2(g_H2[(size_t)n * 32 + cp]);
        s.x += v.x; s.y += v.y;
    }
    sm[t] = s;
    __syncthreads();
    if (t < 32) {
        float2 v = sm[t];
        #pragma unroll
        for (int p = 1; p < 8; p++) {
            float2 u = sm[t + 32 * p];
            v.x += u.x; v.y += u.y;
        }
        int cnt = hi - lo;
        float inv = 1.f / (float)(cnt > 0 ? cnt : 1);
        float2 w = reinterpret_cast<const float2*>(Wl)[t];
        sm[t] = make_float2(v.x * inv * w.x + v.y * inv * w.y, 0.f);
    }
    __syncthreads();
    if (t == 0) {
        float r = 0.f;
        #pragma unroll
        for (int c = 0; c < 32; c++) r += sm[c].x;
        out[g] = r + bl[0];
    }
}

// ---------------- launch: 10 kernels, single stream ----------------
extern "C" void kernel_launch(void* const* d_in, const int* in_sizes, int n_in,
                              void* d_out, int out_size) {
    const float* x     = (const float*)d_in[0];
    const int*   eidx  = (const int*)d_in[1];
    const int*   batch = (const int*)d_in[2];
    const float* W1    = (const float*)d_in[3];
    const float* b1    = (const float*)d_in[4];
    const float* W2    = (const float*)d_in[5];
    const float* b2    = (const float*)d_in[6];
    const float* Wl    = (const float*)d_in[7];
    const float* bl    = (const float*)d_in[8];
    float* out = (float*)d_out;

    const int4* src4 = (const int4*)eidx;
    const int4* dst4 = (const int4*)(eidx + N_EDGES);

    __nv_bfloat162* H1v; cudaGetSymbolAddress((void**)&H1v, g_H1);
    __nv_bfloat162* H2v; cudaGetSymbolAddress((void**)&H2v, g_H2);
    __nv_bfloat162* Pv;  cudaGetSymbolAddress((void**)&Pv,  g_P);
    __nv_bfloat162* P2v; cudaGetSymbolAddress((void**)&P2v, g_P2);

    int nThreads = 256;
    int nbNodes = (N_NODES + nThreads - 1) / nThreads;
    int nbEdge4 = (N_EDGES / 4 + nThreads - 1) / nThreads;
    const int NTB = (N_NODES + 127) / 128;   // 782 mma blocks

    // --- CSC build (5 kernels) ---
    k_zero_deg<<<nbNodes, nThreads>>>();
    k_count<<<nbEdge4, nThreads>>>(dst4);
    k_scanA<<<SCAN_NB, SCAN_B>>>();
    k_scanC<<<SCAN_NB, SCAN_B>>>();
    k_fill<<<nbEdge4, nThreads>>>(src4, dst4);

    // --- layer 1: tensor-core GEMM (X fp32 -> bf16 inline) + gather ---
    k_mma<N_FEAT, true><<<NTB, 256>>>((const void*)x, W1, Pv);
    k_gather<1><<<(N_NODES * 32 + 255) / 256, 256>>>(Pv, H1v, b1);

    // --- layer 2: tensor-core GEMM (H1 bf16 direct) + gather ---
    k_mma<HIDDEN, false><<<NTB, 256>>>((const void*)H1v, W2, P2v);
    k_gather<0><<<(N_NODES * 32 + 255) / 256, 256>>>(P2v, H2v, b2);

    // --- pool + head ---
    k_pool<<<N_GRAPHS, 256>>>(batch, Wl, bl, out);
}

// round 13
// speedup vs baseline: 1.4125x; 1.1058x over previous
#include <cuda_runtime.h>
#include <cuda_bf16.h>
#include <stdint.h>

#define N_NODES  100000
#define N_EDGES  3200000
#define N_FEAT   128
#define HIDDEN   64
#define N_GRAPHS 256

// Padded CSC capacity: E + 3 per node + 8 slack for unroll-8 overread
#define CSC_CAP  (N_EDGES + 4 * N_NODES + 8)
#define NTB      ((N_NODES + 127) / 128)    // 782 mma row-tiles

// ---------------- device scratch ----------------
__device__ __align__(16) static __nv_bfloat162 g_P [N_NODES * 32];  // layer-1 messages
__device__ __align__(16) static __nv_bfloat162 g_P2[N_NODES * 32];  // layer-2 messages
__device__ __align__(16) static __nv_bfloat162 g_H1[N_NODES * 32];  // layer-1 out
__device__ __align__(16) static __nv_bfloat162 g_H2[N_NODES * 32];  // layer-2 out
__device__ __align__(16) static int   g_csc[CSC_CAP];               // pad slots stay 0
__device__              static int   g_deg[N_NODES];
__device__              static int   g_rowptr[N_NODES];
__device__              static int   g_cursor[N_NODES];
__device__              static float g_dinv[N_NODES];
__device__              static int   g_bsum[128];

// ---------------- init ----------------
__global__ void k_zero_deg() {
    int i = blockIdx.x * blockDim.x + threadIdx.x;
    if (i < N_NODES) g_deg[i] = 0;
}

// ---------------- degree histogram, 4 edges/thread ----------------
__global__ void k_count(const int4* __restrict__ dst4) {
    int i = blockIdx.x * blockDim.x + threadIdx.x;
    if (i < N_EDGES / 4) {
        int4 d = dst4[i];
        atomicAdd(&g_deg[d.x], 1);
        atomicAdd(&g_deg[d.y], 1);
        atomicAdd(&g_deg[d.z], 1);
        atomicAdd(&g_deg[d.w], 1);
    }
}

// ---------------- exclusive scan of padded degrees (+ dinv fused) ----------------
#define SCAN_B 1024
#define SCAN_NB ((N_NODES + SCAN_B - 1) / SCAN_B)   // 98

__global__ void k_scanA() {
    __shared__ int sm[SCAN_B];
    int i = blockIdx.x * SCAN_B + threadIdx.x;
    int v = 0;
    if (i < N_NODES) {
        int d = g_deg[i];
        g_dinv[i] = rsqrtf((float)(d + 1));          // fused dinv (self-loop +1)
        v = (d + 3) & ~3;                            // pad segment to multiple of 4
    }
    sm[threadIdx.x] = v;
    __syncthreads();
    #pragma unroll
    for (int off = 1; off < SCAN_B; off <<= 1) {
        int t = (threadIdx.x >= off) ? sm[threadIdx.x - off] : 0;
        __syncthreads();
        sm[threadIdx.x] += t;
        __syncthreads();
    }
    int inc = sm[threadIdx.x];
    if (i < N_NODES) g_rowptr[i] = inc - v;
    if (threadIdx.x == SCAN_B - 1) g_bsum[blockIdx.x] = inc;
}

// scanC with scanB merged: each block computes its own bsum-prefix directly.
__global__ void k_scanC() {
    __shared__ int soff;
    int c = blockIdx.x;
    if (threadIdx.x < 32) {
        int s = 0;
        for (int j = threadIdx.x; j < c; j += 32) s += g_bsum[j];
        #pragma unroll
        for (int o = 16; o; o >>= 1) s += __shfl_down_sync(0xFFFFFFFFu, s, o);
        if (threadIdx.x == 0) soff = s;
    }
    __syncthreads();
    int i = c * SCAN_B + threadIdx.x;
    if (i < N_NODES) {
        int r = g_rowptr[i] + soff;
        g_rowptr[i] = r;
        g_cursor[i] = r;
    }
}

// ---------------- tensor-core GEMM body: P = (A @ W) * dinv, bf16 out -------------
// mma.sync.aligned.m16n8k16.row.col.f32.bf16.bf16.f32
// Warp tile: 16 rows x 64 cols. A fragments straight from global.
// B staged in smem transposed [n][k], stride K+8 elems => conflict-free.

__device__ __forceinline__ unsigned cvt_pack_bf2(float hi, float lo) {
    unsigned r;
    asm("cvt.rn.bf16x2.f32 %0, %1, %2;" : "=r"(r) : "f"(hi), "f"(lo));
    return r;
}

__device__ __forceinline__ void mma16816(float* d, unsigned a0, unsigned a1,
                                         unsigned a2, unsigned a3,
                                         unsigned b0, unsigned b1) {
    asm("mma.sync.aligned.m16n8k16.row.col.f32.bf16.bf16.f32 "
        "{%0,%1,%2,%3}, {%4,%5,%6,%7}, {%8,%9}, {%0,%1,%2,%3};"
        : "+f"(d[0]), "+f"(d[1]), "+f"(d[2]), "+f"(d[3])
        : "r"(a0), "r"(a1), "r"(a2), "r"(a3), "r"(b0), "r"(b1));
}

template <int K, bool A_FP32>
__device__ __forceinline__ void mma_body(const void* __restrict__ Asrc,
                                         const float* __restrict__ W,
                                         __nv_bfloat162* __restrict__ Pout,
                                         __nv_bfloat16* sB,
                                         int tile0, int tstride) {
    constexpr int BSTRIDE = K + 8;                      // conflict-free LDS pattern

    for (int idx = threadIdx.x; idx < K * 64; idx += blockDim.x) {
        int k = idx >> 6, n = idx & 63;                 // W row-major [K][64]
        sB[n * BSTRIDE + k] = __float2bfloat16(W[idx]);
    }
    __syncthreads();

    int warp = threadIdx.x >> 5, lane = threadIdx.x & 31;
    int l4 = lane >> 2, lm = lane & 3;

    for (int tb = tile0; tb < NTB; tb += tstride) {
        int row0 = tb * 128 + warp * 16;
        int ra = row0 + l4;                             // rows for d0/d1
        int rb = ra + 8;                                // rows for d2/d3
        int ca = ra < N_NODES ? ra : N_NODES - 1;       // clamped load rows
        int cb = rb < N_NODES ? rb : N_NODES - 1;

        float acc[32];
        #pragma unroll
        for (int i = 0; i < 32; i++) acc[i] = 0.f;

        #pragma unroll
        for (int ks = 0; ks < K / 16; ks++) {
            int k0 = ks * 16 + lm * 2;
            unsigned a0, a1, a2, a3;
            if (A_FP32) {
                const float* X = (const float*)Asrc;
                float2 fa = *(const float2*)(X + (size_t)ca * K + k0);
                float2 fb = *(const float2*)(X + (size_t)cb * K + k0);
                float2 fc = *(const float2*)(X + (size_t)ca * K + k0 + 8);
                float2 fd = *(const float2*)(X + (size_t)cb * K + k0 + 8);
                a0 = cvt_pack_bf2(fa.y, fa.x);          // hi = k0+1, lo = k0
                a1 = cvt_pack_bf2(fb.y, fb.x);
                a2 = cvt_pack_bf2(fc.y, fc.x);
                a3 = cvt_pack_bf2(fd.y, fd.x);
            } else {
                const __nv_bfloat16* H = (const __nv_bfloat16*)Asrc;
                a0 = *(const unsigned*)(H + (size_t)ca * K + k0);
                a1 = *(const unsigned*)(H + (size_t)cb * K + k0);
                a2 = *(const unsigned*)(H + (size_t)ca * K + k0 + 8);
                a3 = *(const unsigned*)(H + (size_t)cb * K + k0 + 8);
            }
            #pragma unroll
            for (int nt = 0; nt < 8; nt++) {
                const __nv_bfloat16* bp = sB + (nt * 8 + l4) * BSTRIDE + k0;
                unsigned b0 = *(const unsigned*)bp;       // (k0,n),(k0+1,n)
                unsigned b1 = *(const unsigned*)(bp + 8); // (k0+8,n),(k0+9,n)
                mma16816(&acc[nt * 4], a0, a1, a2, a3, b0, b1);
            }
        }

        float da = g_dinv[ca], db = g_dinv[cb];
        #pragma unroll
        for (int nt = 0; nt < 8; nt++) {
            int cp = nt * 4 + lm;                       // col-pair index (c0/2)
            if (ra < N_NODES)
                Pout[ra * 32 + cp] = __floats2bfloat162_rn(acc[nt*4+0]*da, acc[nt*4+1]*da);
            if (rb < N_NODES)
                Pout[rb * 32 + cp] = __floats2bfloat162_rn(acc[nt*4+2]*db, acc[nt*4+3]*db);
        }
    }
}

// ---------------- merged: CSC fill || layer-1 GEMM (role split, no barrier) -------
// After scanC both are runnable: fill needs g_cursor, mma1 needs g_dinv only.
// Role = bid % 5: 4 fill slots : 1 mma slot (work ratio 3125 : 782).
__global__ void k_fill_mma1(const int4* __restrict__ src4, const int4* __restrict__ dst4,
                            const float* __restrict__ X, const float* __restrict__ W1,
                            __nv_bfloat162* __restrict__ Pout) {
    __shared__ __nv_bfloat16 sB[64 * (N_FEAT + 8)];     // 17.4KB (mma role only)
    int grp = blockIdx.x / 5;
    int r   = blockIdx.x % 5;
    if (r < 4) {
        int i = (grp * 4 + r) * 256 + threadIdx.x;
        if (i < N_EDGES / 4) {
            int4 s = src4[i];
            int4 d = dst4[i];
            g_csc[atomicAdd(&g_cursor[d.x], 1)] = s.x;
            g_csc[atomicAdd(&g_cursor[d.y], 1)] = s.y;
            g_csc[atomicAdd(&g_cursor[d.z], 1)] = s.z;
            g_csc[atomicAdd(&g_cursor[d.w], 1)] = s.w;
        }
    } else {
        mma_body<N_FEAT, true>((const void*)X, W1, Pout, sB, grp, NTB);
    }
}

// ---------------- standalone tensor-core GEMM (layer 2) ----------------
template <int K, bool A_FP32>
__global__ void k_mma(const void* __restrict__ Asrc, const float* __restrict__ W,
                      __nv_bfloat162* __restrict__ Pout) {
    __shared__ __nv_bfloat16 sB[64 * (K + 8)];
    mma_body<K, A_FP32>(Asrc, W, Pout, sB, blockIdx.x, gridDim.x);
}

// ---------------- gather-sum aggregation (bf16 messages, fp32 accumulate) ---------
template <int RELU>
__global__ void k_gather(const __nv_bfloat162* __restrict__ P,
                         __nv_bfloat162* __restrict__ Hout,
                         const float* __restrict__ bias) {
    int widx = (blockIdx.x * blockDim.x + threadIdx.x) >> 5;
    if (widx >= N_NODES) return;
    int lane = threadIdx.x & 31;

    float dn = g_dinv[widx];
    int start = g_rowptr[widx];
    int end = start + g_deg[widx];

    float2 acc = __bfloat1622float2(P[widx * 32 + lane]);   // self term

    for (int p = start; p < end; p += 8) {
        int4 sa = *reinterpret_cast<const int4*>(g_csc + p);
        int4 sb = *reinterpret_cast<const int4*>(g_csc + p + 4);
        float2 v0 = __bfloat1622float2(P[(size_t)sa.x * 32 + lane]);
        float2 v1 = __bfloat1622float2(P[(size_t)sa.y * 32 + lane]);
        float2 v2 = __bfloat1622float2(P[(size_t)sa.z * 32 + lane]);
        float2 v3 = __bfloat1622float2(P[(size_t)sa.w * 32 + lane]);
        float2 v4 = __bfloat1622float2(P[(size_t)sb.x * 32 + lane]);
        float2 v5 = __bfloat1622float2(P[(size_t)sb.y * 32 + lane]);
        float2 v6 = __bfloat1622float2(P[(size_t)sb.z * 32 + lane]);
        float2 v7 = __bfloat1622float2(P[(size_t)sb.w * 32 + lane]);
        int rem = end - p;
        acc.x += v0.x; acc.y += v0.y;
        if (rem > 1) { acc.x += v1.x; acc.y += v1.y; }
        if (rem > 2) { acc.x += v2.x; acc.y += v2.y; }
        if (rem > 3) { acc.x += v3.x; acc.y += v3.y; }
        if (rem > 4) { acc.x += v4.x; acc.y += v4.y; }
        if (rem > 5) { acc.x += v5.x; acc.y += v5.y; }
        if (rem > 6) { acc.x += v6.x; acc.y += v6.y; }
        if (rem > 7) { acc.x += v7.x; acc.y += v7.y; }
    }

    float2 b = reinterpret_cast<const float2*>(bias)[lane];
    float ox = dn * acc.x + b.x;
    float oy = dn * acc.y + b.y;
    if (RELU) { ox = fmaxf(ox, 0.f); oy = fmaxf(oy, 0.f); }
    Hout[widx * 32 + lane] = __floats2bfloat162_rn(ox, oy);
}

// ---------------- pool (mean per graph, bf16 in) + final linear ----------------
__device__ __forceinline__ int lbound(const int* __restrict__ a, int n, int key) {
    int lo = 0, hi = n;
    while (lo < hi) {
        int m = (lo + hi) >> 1;
        if (a[m] < key) lo = m + 1; else hi = m;
    }
    return lo;
}

__global__ void k_pool(const int* __restrict__ batch,
                       const float* __restrict__ Wl, const float* __restrict__ bl,
                       float* __restrict__ out) {
    __shared__ float2 sm[256];               // 8 partitions x 32 col-pairs
    int g = blockIdx.x;
    int t = threadIdx.x;                     // 256 threads
    int lo = lbound(batch, N_NODES, g);
    int hi = lbound(batch, N_NODES, g + 1);

    int cp   = t & 31;
    int part = t >> 5;
    float2 s = make_float2(0.f, 0.f);
    for (int n = lo + part; n < hi; n += 8) {
        float2 v = __bfloat1622float2(g_H2[(size_t)n * 32 + cp]);
        s.x += v.x; s.y += v.y;
    }
    sm[t] = s;
    __syncthreads();
    if (t < 32) {
        float2 v = sm[t];
        #pragma unroll
        for (int p = 1; p < 8; p++) {
            float2 u = sm[t + 32 * p];
            v.x += u.x; v.y += u.y;
        }
        int cnt = hi - lo;
        float inv = 1.f / (float)(cnt > 0 ? cnt : 1);
        float2 w = reinterpret_cast<const float2*>(Wl)[t];
        sm[t] = make_float2(v.x * inv * w.x + v.y * inv * w.y, 0.f);
    }
    __syncthreads();
    if (t == 0) {
        float r = 0.f;
        #pragma unroll
        for (int c = 0; c < 32; c++) r += sm[c].x;
        out[g] = r + bl[0];
    }
}

// ---------------- launch: 9 kernels, single stream ----------------
extern "C" void kernel_launch(void* const* d_in, const int* in_sizes, int n_in,
                              void* d_out, int out_size) {
    const float* x     = (const float*)d_in[0];
    const int*   eidx  = (const int*)d_in[1];
    const int*   batch = (const int*)d_in[2];
    const float* W1    = (const float*)d_in[3];
    const float* b1    = (const float*)d_in[4];
    const float* W2    = (const float*)d_in[5];
    const float* b2    = (const float*)d_in[6];
    const float* Wl    = (const float*)d_in[7];
    const float* bl    = (const float*)d_in[8];
    float* out = (float*)d_out;

    const int4* src4 = (const int4*)eidx;
    const int4* dst4 = (const int4*)(eidx + N_EDGES);

    __nv_bfloat162* H1v; cudaGetSymbolAddress((void**)&H1v, g_H1);
    __nv_bfloat162* H2v; cudaGetSymbolAddress((void**)&H2v, g_H2);
    __nv_bfloat162* Pv;  cudaGetSymbolAddress((void**)&Pv,  g_P);
    __nv_bfloat162* P2v; cudaGetSymbolAddress((void**)&P2v, g_P2);

    int nThreads = 256;
    int nbNodes = (N_NODES + nThreads - 1) / nThreads;
    int nbEdge4 = (N_EDGES / 4 + nThreads - 1) / nThreads;

    // --- CSC build prefix (deg/scan) ---
    k_zero_deg<<<nbNodes, nThreads>>>();
    k_count<<<nbEdge4, nThreads>>>(dst4);
    k_scanA<<<SCAN_NB, SCAN_B>>>();
    k_scanC<<<SCAN_NB, SCAN_B>>>();

    // --- CSC fill || layer-1 GEMM (role-split, no dependency between them) ---
    k_fill_mma1<<<NTB * 5, 256>>>(src4, dst4, x, W1, Pv);

    // --- layer 1 gather ---
    k_gather<1><<<(N_NODES * 32 + 255) / 256, 256>>>(Pv, H1v, b1);

    // --- layer 2: tensor-core GEMM (H1 bf16 direct) + gather ---
    k_mma<HIDDEN, false><<<NTB, 256>>>((const void*)H1v, W2, P2v);
    k_gather<0><<<(N_NODES * 32 + 255) / 256, 256>>>(P2v, H2v, b2);

    // --- pool + head ---
    k_pool<<<N_GRAPHS, 256>>>(batch, Wl, bl, out);
}